// round 1
// baseline (speedup 1.0000x reference)
#include <cuda_runtime.h>
#include <math.h>

// Problem dims
#define MROWS   8192      // B*T
#define DMODEL  1024
#define DQKVG   4096
#define NHEADS  16
#define DHEAD   64
#define TLEN    2048
#define BATCHSZ 4

// Scratch (device globals — allocation-free per harness rules)
__device__ __align__(256) float g_xn[(size_t)MROWS * DMODEL];
__device__ __align__(256) float g_qkvg[(size_t)MROWS * DQKVG];
__device__ __align__(256) float g_og[(size_t)MROWS * DMODEL];

// ---------------------------------------------------------------------------
// LayerNorm: one block per row, 256 threads, 1 float4 per thread (1024 cols)
// ---------------------------------------------------------------------------
__global__ __launch_bounds__(256) void ln_kernel(const float* __restrict__ x,
                                                 const float* __restrict__ gamma,
                                                 const float* __restrict__ beta) {
    int row = blockIdx.x;
    int t = threadIdx.x;
    const float4* xr = (const float4*)(x + (size_t)row * DMODEL);
    float4 a = xr[t];
    float s = a.x + a.y + a.z + a.w;
    float q = a.x * a.x + a.y * a.y + a.z * a.z + a.w * a.w;
    #pragma unroll
    for (int o = 16; o > 0; o >>= 1) {
        s += __shfl_xor_sync(0xffffffffu, s, o);
        q += __shfl_xor_sync(0xffffffffu, q, o);
    }
    __shared__ float ss[8], sq[8];
    int w = t >> 5, lane = t & 31;
    if (lane == 0) { ss[w] = s; sq[w] = q; }
    __syncthreads();
    float st = 0.f, qt = 0.f;
    #pragma unroll
    for (int i = 0; i < 8; i++) { st += ss[i]; qt += sq[i]; }
    float mu = st * (1.0f / DMODEL);
    float var = qt * (1.0f / DMODEL) - mu * mu;
    float rs = rsqrtf(var + 1e-5f);
    float4 gm = ((const float4*)gamma)[t];
    float4 bt = ((const float4*)beta)[t];
    float4 o;
    o.x = (a.x - mu) * rs * gm.x + bt.x;
    o.y = (a.y - mu) * rs * gm.y + bt.y;
    o.z = (a.z - mu) * rs * gm.z + bt.z;
    o.w = (a.w - mu) * rs * gm.w + bt.w;
    ((float4*)(g_xn + (size_t)row * DMODEL))[t] = o;
}

// ---------------------------------------------------------------------------
// Fused QKVG GEMM: g_qkvg[m, 0:4096] = g_xn[m,:] @ [WQ;WK;WV;Wg]^T + bias
// silu applied to the G block (cols 3072..4095).
// 128x128 block tile, BK=16, 256 threads, 8x8 per-thread microtile.
// ---------------------------------------------------------------------------
__global__ __launch_bounds__(256) void gemm_qkvg(
    const float* __restrict__ WQ, const float* __restrict__ bQ,
    const float* __restrict__ WK, const float* __restrict__ bK,
    const float* __restrict__ WV, const float* __restrict__ bV,
    const float* __restrict__ Wg, const float* __restrict__ bg) {
    __shared__ float As[16][132];
    __shared__ float Bs[16][132];

    int tid = threadIdx.x;
    int tx = tid & 15, ty = tid >> 4;
    int bm = blockIdx.y, bn = blockIdx.x;

    int which = (bn * 128) >> 10;
    const float* W;  const float* bias;
    if      (which == 0) { W = WQ; bias = bQ; }
    else if (which == 1) { W = WK; bias = bK; }
    else if (which == 2) { W = WV; bias = bV; }
    else                 { W = Wg; bias = bg; }
    int wrow0 = (bn * 128) & 1023;

    const float* Ab = g_xn + (size_t)(bm * 128) * DMODEL;
    const float* Wb = W + (size_t)wrow0 * DMODEL;

    float acc[8][8];
    #pragma unroll
    for (int i = 0; i < 8; i++)
        #pragma unroll
        for (int j = 0; j < 8; j++) acc[i][j] = 0.f;

    for (int k0 = 0; k0 < DMODEL; k0 += 16) {
        #pragma unroll
        for (int i = 0; i < 2; i++) {
            int idx4 = tid + i * 256;           // 0..511
            int m = idx4 >> 2;
            int kq = (idx4 & 3) << 2;
            float4 av = *(const float4*)(Ab + (size_t)m * DMODEL + k0 + kq);
            As[kq + 0][m] = av.x; As[kq + 1][m] = av.y;
            As[kq + 2][m] = av.z; As[kq + 3][m] = av.w;
            float4 wv = *(const float4*)(Wb + (size_t)m * DMODEL + k0 + kq);
            Bs[kq + 0][m] = wv.x; Bs[kq + 1][m] = wv.y;
            Bs[kq + 2][m] = wv.z; Bs[kq + 3][m] = wv.w;
        }
        __syncthreads();
        #pragma unroll
        for (int k = 0; k < 16; k++) {
            float ra[8], rb[8];
            #pragma unroll
            for (int i = 0; i < 4; i++) {
                ra[i]     = As[k][ty * 4 + i];
                ra[i + 4] = As[k][64 + ty * 4 + i];
                rb[i]     = Bs[k][tx * 4 + i];
                rb[i + 4] = Bs[k][64 + tx * 4 + i];
            }
            #pragma unroll
            for (int i = 0; i < 8; i++)
                #pragma unroll
                for (int j = 0; j < 8; j++)
                    acc[i][j] = fmaf(ra[i], rb[j], acc[i][j]);
        }
        __syncthreads();
    }

    #pragma unroll
    for (int i = 0; i < 8; i++) {
        int rm = (i < 4) ? (ty * 4 + i) : (64 + ty * 4 + (i - 4));
        size_t row = (size_t)(bm * 128 + rm);
        #pragma unroll
        for (int j = 0; j < 8; j++) {
            int cn = (j < 4) ? (tx * 4 + j) : (64 + tx * 4 + (j - 4));
            int colg = bn * 128 + cn;
            float v = acc[i][j] + bias[colg & 1023];
            if (which == 3) v = v / (1.0f + expf(-v));   // silu
            g_qkvg[row * DQKVG + colg] = v;
        }
    }
}

// ---------------------------------------------------------------------------
// Scan: one block per (b, head); 64 threads, thread d owns h[0:64][d] in regs.
// h = alpha*h + k outer v; o = q . h ; write o * silu_gate.
// ---------------------------------------------------------------------------
__global__ __launch_bounds__(64) void scan_kernel(const float* __restrict__ alpha_logit) {
    int b  = blockIdx.x >> 4;
    int hh = blockIdx.x & 15;
    int d  = threadIdx.x;

    __shared__ float qs[64], ks[64], alsh[64];
    alsh[d] = 1.0f / (1.0f + expf(-alpha_logit[hh * 64 + d]));
    __syncthreads();

    float alr[64];
    #pragma unroll
    for (int s = 0; s < 64; s++) alr[s] = alsh[s];

    float h[64];
    #pragma unroll
    for (int s = 0; s < 64; s++) h[s] = 0.f;

    const float* base = g_qkvg + (size_t)b * TLEN * DQKVG + hh * 64;
    float* ogb = g_og + (size_t)b * TLEN * DMODEL + hh * 64 + d;

    for (int t = 0; t < TLEN; t++) {
        const float* row = base + (size_t)t * DQKVG;
        float v = row[2048 + d];
        float g = row[3072 + d];          // already silu'd
        qs[d] = row[d];
        ks[d] = row[1024 + d];
        __syncthreads();
        float o = 0.f;
        #pragma unroll
        for (int s = 0; s < 64; s++) {
            h[s] = fmaf(ks[s], v, alr[s] * h[s]);
            o = fmaf(qs[s], h[s], o);
        }
        ogb[(size_t)t * DMODEL] = o * g;
        __syncthreads();
    }
}

// ---------------------------------------------------------------------------
// Output GEMM: out = g_og @ WO^T + bO + x  (residual)
// ---------------------------------------------------------------------------
__global__ __launch_bounds__(256) void gemm_out(
    const float* __restrict__ WO, const float* __restrict__ bO,
    const float* __restrict__ x, float* __restrict__ out) {
    __shared__ float As[16][132];
    __shared__ float Bs[16][132];

    int tid = threadIdx.x;
    int tx = tid & 15, ty = tid >> 4;
    int bm = blockIdx.y, bn = blockIdx.x;

    const float* Ab = g_og + (size_t)(bm * 128) * DMODEL;
    const float* Wb = WO + (size_t)(bn * 128) * DMODEL;

    float acc[8][8];
    #pragma unroll
    for (int i = 0; i < 8; i++)
        #pragma unroll
        for (int j = 0; j < 8; j++) acc[i][j] = 0.f;

    for (int k0 = 0; k0 < DMODEL; k0 += 16) {
        #pragma unroll
        for (int i = 0; i < 2; i++) {
            int idx4 = tid + i * 256;
            int m = idx4 >> 2;
            int kq = (idx4 & 3) << 2;
            float4 av = *(const float4*)(Ab + (size_t)m * DMODEL + k0 + kq);
            As[kq + 0][m] = av.x; As[kq + 1][m] = av.y;
            As[kq + 2][m] = av.z; As[kq + 3][m] = av.w;
            float4 wv = *(const float4*)(Wb + (size_t)m * DMODEL + k0 + kq);
            Bs[kq + 0][m] = wv.x; Bs[kq + 1][m] = wv.y;
            Bs[kq + 2][m] = wv.z; Bs[kq + 3][m] = wv.w;
        }
        __syncthreads();
        #pragma unroll
        for (int k = 0; k < 16; k++) {
            float ra[8], rb[8];
            #pragma unroll
            for (int i = 0; i < 4; i++) {
                ra[i]     = As[k][ty * 4 + i];
                ra[i + 4] = As[k][64 + ty * 4 + i];
                rb[i]     = Bs[k][tx * 4 + i];
                rb[i + 4] = Bs[k][64 + tx * 4 + i];
            }
            #pragma unroll
            for (int i = 0; i < 8; i++)
                #pragma unroll
                for (int j = 0; j < 8; j++)
                    acc[i][j] = fmaf(ra[i], rb[j], acc[i][j]);
        }
        __syncthreads();
    }

    #pragma unroll
    for (int i = 0; i < 8; i++) {
        int rm = (i < 4) ? (ty * 4 + i) : (64 + ty * 4 + (i - 4));
        size_t row = (size_t)(bm * 128 + rm);
        #pragma unroll
        for (int j = 0; j < 8; j++) {
            int cn = (j < 4) ? (tx * 4 + j) : (64 + tx * 4 + (j - 4));
            int colg = bn * 128 + cn;
            float v = acc[i][j] + bO[colg] + x[row * DMODEL + colg];
            out[row * DMODEL + colg] = v;
        }
    }
}

// ---------------------------------------------------------------------------
extern "C" void kernel_launch(void* const* d_in, const int* in_sizes, int n_in,
                              void* d_out, int out_size) {
    const float* x      = (const float*)d_in[0];
    const float* WQ     = (const float*)d_in[1];
    const float* bQ     = (const float*)d_in[2];
    const float* WK     = (const float*)d_in[3];
    const float* bK     = (const float*)d_in[4];
    const float* WV     = (const float*)d_in[5];
    const float* bV     = (const float*)d_in[6];
    const float* WO     = (const float*)d_in[7];
    const float* bO     = (const float*)d_in[8];
    const float* Wg     = (const float*)d_in[9];
    const float* bg     = (const float*)d_in[10];
    const float* alpha  = (const float*)d_in[11];
    const float* gamma  = (const float*)d_in[12];
    const float* beta   = (const float*)d_in[13];
    float* out = (float*)d_out;

    ln_kernel<<<MROWS, 256>>>(x, gamma, beta);

    dim3 g1(DQKVG / 128, MROWS / 128);
    gemm_qkvg<<<g1, 256>>>(WQ, bQ, WK, bK, WV, bV, Wg, bg);

    scan_kernel<<<BATCHSZ * NHEADS, 64>>>(alpha);

    dim3 g2(DMODEL / 128, MROWS / 128);
    gemm_out<<<g2, 256>>>(WO, bO, x, out);
}

// round 4
// speedup vs baseline: 1.6116x; 1.6116x over previous
#include <cuda_runtime.h>
#include <math.h>

// Problem dims
#define MROWS   8192      // B*T
#define DMODEL  1024
#define DQKVG   4096
#define NHEADS  16
#define DHEAD   64
#define TLEN    2048
#define BATCHSZ 4
#define CHUNK   64
#define NCHUNK  (TLEN / CHUNK)   // 32

// Scratch (device globals — allocation-free per harness rules)
__device__ __align__(256) float g_xn[(size_t)MROWS * DMODEL];
__device__ __align__(256) float g_qkvg[(size_t)MROWS * DQKVG];
__device__ __align__(256) float g_og[(size_t)MROWS * DMODEL];
// per-chunk state summaries and initial states: [B*NH][NCHUNK][64*64]
__device__ __align__(256) float g_chunkS[(size_t)BATCHSZ * NHEADS * NCHUNK * 64 * 64];
__device__ __align__(256) float g_state [(size_t)BATCHSZ * NHEADS * NCHUNK * 64 * 64];

// ---------------------------------------------------------------------------
// LayerNorm: one block per row, 256 threads, 1 float4 per thread (1024 cols)
// ---------------------------------------------------------------------------
__global__ __launch_bounds__(256) void ln_kernel(const float* __restrict__ x,
                                                 const float* __restrict__ gamma,
                                                 const float* __restrict__ beta) {
    int row = blockIdx.x;
    int t = threadIdx.x;
    const float4* xr = (const float4*)(x + (size_t)row * DMODEL);
    float4 a = xr[t];
    float s = a.x + a.y + a.z + a.w;
    float q = a.x * a.x + a.y * a.y + a.z * a.z + a.w * a.w;
    #pragma unroll
    for (int o = 16; o > 0; o >>= 1) {
        s += __shfl_xor_sync(0xffffffffu, s, o);
        q += __shfl_xor_sync(0xffffffffu, q, o);
    }
    __shared__ float ss[8], sq[8];
    int w = t >> 5, lane = t & 31;
    if (lane == 0) { ss[w] = s; sq[w] = q; }
    __syncthreads();
    float st = 0.f, qt = 0.f;
    #pragma unroll
    for (int i = 0; i < 8; i++) { st += ss[i]; qt += sq[i]; }
    float mu = st * (1.0f / DMODEL);
    float var = qt * (1.0f / DMODEL) - mu * mu;
    float rs = rsqrtf(var + 1e-5f);
    float4 gm = ((const float4*)gamma)[t];
    float4 bt = ((const float4*)beta)[t];
    float4 o;
    o.x = (a.x - mu) * rs * gm.x + bt.x;
    o.y = (a.y - mu) * rs * gm.y + bt.y;
    o.z = (a.z - mu) * rs * gm.z + bt.z;
    o.w = (a.w - mu) * rs * gm.w + bt.w;
    ((float4*)(g_xn + (size_t)row * DMODEL))[t] = o;
}

// ---------------------------------------------------------------------------
// Fused QKVG GEMM (unchanged this round)
// ---------------------------------------------------------------------------
__global__ __launch_bounds__(256) void gemm_qkvg(
    const float* __restrict__ WQ, const float* __restrict__ bQ,
    const float* __restrict__ WK, const float* __restrict__ bK,
    const float* __restrict__ WV, const float* __restrict__ bV,
    const float* __restrict__ Wg, const float* __restrict__ bg) {
    __shared__ float As[16][132];
    __shared__ float Bs[16][132];

    int tid = threadIdx.x;
    int tx = tid & 15, ty = tid >> 4;
    int bm = blockIdx.y, bn = blockIdx.x;

    int which = (bn * 128) >> 10;
    const float* W;  const float* bias;
    if      (which == 0) { W = WQ; bias = bQ; }
    else if (which == 1) { W = WK; bias = bK; }
    else if (which == 2) { W = WV; bias = bV; }
    else                 { W = Wg; bias = bg; }
    int wrow0 = (bn * 128) & 1023;

    const float* Ab = g_xn + (size_t)(bm * 128) * DMODEL;
    const float* Wb = W + (size_t)wrow0 * DMODEL;

    float acc[8][8];
    #pragma unroll
    for (int i = 0; i < 8; i++)
        #pragma unroll
        for (int j = 0; j < 8; j++) acc[i][j] = 0.f;

    for (int k0 = 0; k0 < DMODEL; k0 += 16) {
        #pragma unroll
        for (int i = 0; i < 2; i++) {
            int idx4 = tid + i * 256;
            int m = idx4 >> 2;
            int kq = (idx4 & 3) << 2;
            float4 av = *(const float4*)(Ab + (size_t)m * DMODEL + k0 + kq);
            As[kq + 0][m] = av.x; As[kq + 1][m] = av.y;
            As[kq + 2][m] = av.z; As[kq + 3][m] = av.w;
            float4 wv = *(const float4*)(Wb + (size_t)m * DMODEL + k0 + kq);
            Bs[kq + 0][m] = wv.x; Bs[kq + 1][m] = wv.y;
            Bs[kq + 2][m] = wv.z; Bs[kq + 3][m] = wv.w;
        }
        __syncthreads();
        #pragma unroll
        for (int k = 0; k < 16; k++) {
            float ra[8], rb[8];
            #pragma unroll
            for (int i = 0; i < 4; i++) {
                ra[i]     = As[k][ty * 4 + i];
                ra[i + 4] = As[k][64 + ty * 4 + i];
                rb[i]     = Bs[k][tx * 4 + i];
                rb[i + 4] = Bs[k][64 + tx * 4 + i];
            }
            #pragma unroll
            for (int i = 0; i < 8; i++)
                #pragma unroll
                for (int j = 0; j < 8; j++)
                    acc[i][j] = fmaf(ra[i], rb[j], acc[i][j]);
        }
        __syncthreads();
    }

    #pragma unroll
    for (int i = 0; i < 8; i++) {
        int rm = (i < 4) ? (ty * 4 + i) : (64 + ty * 4 + (i - 4));
        size_t row = (size_t)(bm * 128 + rm);
        #pragma unroll
        for (int j = 0; j < 8; j++) {
            int cn = (j < 4) ? (tx * 4 + j) : (64 + tx * 4 + (j - 4));
            int colg = bn * 128 + cn;
            float v = acc[i][j] + bias[colg & 1023];
            if (which == 3) v = v / (1.0f + expf(-v));   // silu
            g_qkvg[row * DQKVG + colg] = v;
        }
    }
}

// ---------------------------------------------------------------------------
// Pass 1: per-chunk state summary S_c[s,d] = sum_u alpha_s^(63-u) k_u[s] v_u[d]
// One block per (b, head, chunk). 256 threads, each a 4x4 microtile of 64x64.
// NOTE: all smem stores into 65-pitch arrays are SCALAR (float4 would be
// misaligned: 65*4 = 260-byte row pitch).
// ---------------------------------------------------------------------------
__global__ __launch_bounds__(256) void chunk_summary(const float* __restrict__ alpha_logit) {
    int c = blockIdx.x & (NCHUNK - 1);
    int h = (blockIdx.x >> 5) & (NHEADS - 1);
    int b = blockIdx.x >> 9;

    __shared__ float Kt[64][65];   // [u][s], decayed
    __shared__ float Vs[64][65];   // [u][d]
    __shared__ float lal[64];

    int tid = threadIdx.x;
    int tx = tid & 15, ty = tid >> 4;

    if (tid < 64) {
        float a = 1.0f / (1.0f + expf(-alpha_logit[h * 64 + tid]));
        lal[tid] = log2f(a);
    }
    __syncthreads();

    const float* rowb = g_qkvg + ((size_t)(b * TLEN + c * CHUNK)) * DQKVG + h * 64;
    #pragma unroll
    for (int i = 0; i < 4; i++) {
        int idx = tid + i * 256;           // 0..1023
        int u = idx >> 4;
        int s4 = (idx & 15) << 2;
        const float* r = rowb + (size_t)u * DQKVG;
        float4 kv = *(const float4*)(r + 1024 + s4);
        float4 vv = *(const float4*)(r + 2048 + s4);
        float e = (float)(63 - u);
        Kt[u][s4 + 0] = kv.x * exp2f(lal[s4 + 0] * e);
        Kt[u][s4 + 1] = kv.y * exp2f(lal[s4 + 1] * e);
        Kt[u][s4 + 2] = kv.z * exp2f(lal[s4 + 2] * e);
        Kt[u][s4 + 3] = kv.w * exp2f(lal[s4 + 3] * e);
        Vs[u][s4 + 0] = vv.x;
        Vs[u][s4 + 1] = vv.y;
        Vs[u][s4 + 2] = vv.z;
        Vs[u][s4 + 3] = vv.w;
    }
    __syncthreads();

    float acc[4][4];
    #pragma unroll
    for (int i = 0; i < 4; i++)
        #pragma unroll
        for (int j = 0; j < 4; j++) acc[i][j] = 0.f;

    #pragma unroll 8
    for (int u = 0; u < 64; u++) {
        float ra[4], rb[4];
        #pragma unroll
        for (int i = 0; i < 4; i++) {
            ra[i] = Kt[u][ty * 4 + i];     // s index
            rb[i] = Vs[u][tx * 4 + i];     // d index
        }
        #pragma unroll
        for (int i = 0; i < 4; i++)
            #pragma unroll
            for (int j = 0; j < 4; j++)
                acc[i][j] = fmaf(ra[i], rb[j], acc[i][j]);
    }

    size_t ob = ((size_t)((b * NHEADS + h) * NCHUNK + c)) * 4096;
    #pragma unroll
    for (int i = 0; i < 4; i++)
        #pragma unroll
        for (int j = 0; j < 4; j++)
            g_chunkS[ob + (ty * 4 + i) * 64 + tx * 4 + j] = acc[i][j];
}

// ---------------------------------------------------------------------------
// Pass 2: sequential combine over 32 chunks (per b,head).
// H_{c} = initial state of chunk c;  H_{c+1} = alpha^64 * H_c + S_c.
// 64 blocks, 256 threads, 16 (s,d) elements per thread as 4 float4.
// ---------------------------------------------------------------------------
__global__ __launch_bounds__(256) void chunk_combine(const float* __restrict__ alpha_logit) {
    int bh = blockIdx.x;
    int h = bh & (NHEADS - 1);
    int tid = threadIdx.x;

    float4 H[4];
    float aL[4];
    #pragma unroll
    for (int k = 0; k < 4; k++) {
        H[k] = make_float4(0.f, 0.f, 0.f, 0.f);
        int s = (tid + k * 256) >> 4;      // float4 index -> s
        float a = 1.0f / (1.0f + expf(-alpha_logit[h * 64 + s]));
        aL[k] = exp2f(log2f(a) * 64.0f);
    }

    for (int c = 0; c < NCHUNK; c++) {
        size_t base = ((size_t)bh * NCHUNK + c) * 4096;
        #pragma unroll
        for (int k = 0; k < 4; k++) {
            int idx4 = tid + k * 256;
            ((float4*)(g_state + base))[idx4] = H[k];
            float4 S = ((const float4*)(g_chunkS + base))[idx4];
            H[k].x = aL[k] * H[k].x + S.x;
            H[k].y = aL[k] * H[k].y + S.y;
            H[k].z = aL[k] * H[k].z + S.z;
            H[k].w = aL[k] * H[k].w + S.w;
        }
    }
}

// ---------------------------------------------------------------------------
// Pass 3: intra-chunk output.
//   o_t[d] = sum_{u<=t} (q_t.k_u decayed) V[u][d] + sum_s q_t[s] a^(t+1) H[s][d]
// scores via q~ = q*a^t, k~ = k*a^(-u). One block per (b,head,chunk).
// Dynamic smem ~100KB: Qt[64][65], Ks[64][65], Ms[128][65], NN[128][65].
// All smem writes into 65-pitch arrays are SCALAR (alignment).
// ---------------------------------------------------------------------------
__global__ __launch_bounds__(256) void chunk_output(const float* __restrict__ alpha_logit) {
    extern __shared__ float sm[];
    float (*Qt)[65] = (float(*)[65])(sm);            // [s][t] = q * a^t
    float (*Ks)[65] = (float(*)[65])(sm + 4160);     // [s][u] = k * a^(-u)
    float (*Ms)[65] = (float(*)[65])(sm + 8320);     // [j][t]: j<64 scores, j>=64 q2
    float (*NN)[65] = (float(*)[65])(sm + 16640);    // [j][d]: j<64 V, j>=64 H

    __shared__ float al[64], lal[64];

    int c = blockIdx.x & (NCHUNK - 1);
    int h = (blockIdx.x >> 5) & (NHEADS - 1);
    int b = blockIdx.x >> 9;

    int tid = threadIdx.x;
    int tx = tid & 15, ty = tid >> 4;

    if (tid < 64) {
        float a = 1.0f / (1.0f + expf(-alpha_logit[h * 64 + tid]));
        al[tid] = a;
        lal[tid] = log2f(a);
    }
    __syncthreads();

    const float* rowb = g_qkvg + ((size_t)(b * TLEN + c * CHUNK)) * DQKVG + h * 64;
    size_t sbase = ((size_t)((b * NHEADS + h) * NCHUNK + c)) * 4096;

    #pragma unroll
    for (int i = 0; i < 4; i++) {
        int idx = tid + i * 256;           // 0..1023
        int t = idx >> 4;
        int s4 = (idx & 15) << 2;
        const float* r = rowb + (size_t)t * DQKVG;
        float4 qv = *(const float4*)(r + s4);
        float4 kv = *(const float4*)(r + 1024 + s4);
        float4 vv = *(const float4*)(r + 2048 + s4);
        float tf = (float)t;
        Qt[s4 + 0][t] = qv.x * exp2f(lal[s4 + 0] * tf);
        Qt[s4 + 1][t] = qv.y * exp2f(lal[s4 + 1] * tf);
        Qt[s4 + 2][t] = qv.z * exp2f(lal[s4 + 2] * tf);
        Qt[s4 + 3][t] = qv.w * exp2f(lal[s4 + 3] * tf);
        Ks[s4 + 0][t] = kv.x * exp2f(-lal[s4 + 0] * tf);
        Ks[s4 + 1][t] = kv.y * exp2f(-lal[s4 + 1] * tf);
        Ks[s4 + 2][t] = kv.z * exp2f(-lal[s4 + 2] * tf);
        Ks[s4 + 3][t] = kv.w * exp2f(-lal[s4 + 3] * tf);
        NN[t][s4 + 0] = vv.x;                            // V rows
        NN[t][s4 + 1] = vv.y;
        NN[t][s4 + 2] = vv.z;
        NN[t][s4 + 3] = vv.w;
        float4 hv = *(const float4*)(g_state + sbase + (size_t)idx * 4);
        NN[64 + t][s4 + 0] = hv.x;                       // H rows
        NN[64 + t][s4 + 1] = hv.y;
        NN[64 + t][s4 + 2] = hv.z;
        NN[64 + t][s4 + 3] = hv.w;
    }
    __syncthreads();

    // GEMM1: scores[t][u] = sum_s Qt[s][t] * Ks[s][u]
    float acc[4][4];
    #pragma unroll
    for (int i = 0; i < 4; i++)
        #pragma unroll
        for (int j = 0; j < 4; j++) acc[i][j] = 0.f;

    #pragma unroll 8
    for (int s = 0; s < 64; s++) {
        float ra[4], rb[4];
        #pragma unroll
        for (int i = 0; i < 4; i++) {
            ra[i] = Qt[s][ty * 4 + i];     // t
            rb[i] = Ks[s][tx * 4 + i];     // u
        }
        #pragma unroll
        for (int i = 0; i < 4; i++)
            #pragma unroll
            for (int j = 0; j < 4; j++)
                acc[i][j] = fmaf(ra[i], rb[j], acc[i][j]);
    }

    // masked scores -> Ms[u][t]
    #pragma unroll
    for (int i = 0; i < 4; i++) {
        int t = ty * 4 + i;
        #pragma unroll
        for (int j = 0; j < 4; j++) {
            int u = tx * 4 + j;
            Ms[u][t] = (u <= t) ? acc[i][j] : 0.f;
        }
    }
    // q2 rows: Ms[64+s][t] = Qt[s][t] * a_s  (= q * a^(t+1))
    #pragma unroll
    for (int i = 0; i < 4; i++) {
        int idx = tid + i * 256;
        int s = idx >> 4;
        int t4 = (idx & 15) << 2;
        float a = al[s];
        #pragma unroll
        for (int j = 0; j < 4; j++)
            Ms[64 + s][t4 + j] = Qt[s][t4 + j] * a;
    }
    __syncthreads();

    // GEMM2: o[t][d] = sum_j Ms[j][t] * NN[j][d], j in [0,128)
    float o[4][4];
    #pragma unroll
    for (int i = 0; i < 4; i++)
        #pragma unroll
        for (int j = 0; j < 4; j++) o[i][j] = 0.f;

    #pragma unroll 8
    for (int jj = 0; jj < 128; jj++) {
        float ra[4], rb[4];
        #pragma unroll
        for (int i = 0; i < 4; i++) {
            ra[i] = Ms[jj][ty * 4 + i];    // t
            rb[i] = NN[jj][tx * 4 + i];    // d
        }
        #pragma unroll
        for (int i = 0; i < 4; i++)
            #pragma unroll
            for (int j = 0; j < 4; j++)
                o[i][j] = fmaf(ra[i], rb[j], o[i][j]);
    }

    // epilogue: multiply by silu gate and write g_og
    float* ogb = g_og + ((size_t)(b * TLEN + c * CHUNK)) * DMODEL + h * 64;
    #pragma unroll
    for (int i = 0; i < 4; i++) {
        int t = ty * 4 + i;
        const float* gr = rowb + (size_t)t * DQKVG + 3072 + tx * 4;
        float4 g = *(const float4*)gr;
        float4 ov;
        ov.x = o[i][0] * g.x;
        ov.y = o[i][1] * g.y;
        ov.z = o[i][2] * g.z;
        ov.w = o[i][3] * g.w;
        *(float4*)(ogb + (size_t)t * DMODEL + tx * 4) = ov;
    }
}

// ---------------------------------------------------------------------------
// Output GEMM: out = g_og @ WO^T + bO + x  (residual) (unchanged)
// ---------------------------------------------------------------------------
__global__ __launch_bounds__(256) void gemm_out(
    const float* __restrict__ WO, const float* __restrict__ bO,
    const float* __restrict__ x, float* __restrict__ out) {
    __shared__ float As[16][132];
    __shared__ float Bs[16][132];

    int tid = threadIdx.x;
    int tx = tid & 15, ty = tid >> 4;
    int bm = blockIdx.y, bn = blockIdx.x;

    const float* Ab = g_og + (size_t)(bm * 128) * DMODEL;
    const float* Wb = WO + (size_t)(bn * 128) * DMODEL;

    float acc[8][8];
    #pragma unroll
    for (int i = 0; i < 8; i++)
        #pragma unroll
        for (int j = 0; j < 8; j++) acc[i][j] = 0.f;

    for (int k0 = 0; k0 < DMODEL; k0 += 16) {
        #pragma unroll
        for (int i = 0; i < 2; i++) {
            int idx4 = tid + i * 256;
            int m = idx4 >> 2;
            int kq = (idx4 & 3) << 2;
            float4 av = *(const float4*)(Ab + (size_t)m * DMODEL + k0 + kq);
            As[kq + 0][m] = av.x; As[kq + 1][m] = av.y;
            As[kq + 2][m] = av.z; As[kq + 3][m] = av.w;
            float4 wv = *(const float4*)(Wb + (size_t)m * DMODEL + k0 + kq);
            Bs[kq + 0][m] = wv.x; Bs[kq + 1][m] = wv.y;
            Bs[kq + 2][m] = wv.z; Bs[kq + 3][m] = wv.w;
        }
        __syncthreads();
        #pragma unroll
        for (int k = 0; k < 16; k++) {
            float ra[8], rb[8];
            #pragma unroll
            for (int i = 0; i < 4; i++) {
                ra[i]     = As[k][ty * 4 + i];
                ra[i + 4] = As[k][64 + ty * 4 + i];
                rb[i]     = Bs[k][tx * 4 + i];
                rb[i + 4] = Bs[k][64 + tx * 4 + i];
            }
            #pragma unroll
            for (int i = 0; i < 8; i++)
                #pragma unroll
                for (int j = 0; j < 8; j++)
                    acc[i][j] = fmaf(ra[i], rb[j], acc[i][j]);
        }
        __syncthreads();
    }

    #pragma unroll
    for (int i = 0; i < 8; i++) {
        int rm = (i < 4) ? (ty * 4 + i) : (64 + ty * 4 + (i - 4));
        size_t row = (size_t)(bm * 128 + rm);
        #pragma unroll
        for (int j = 0; j < 8; j++) {
            int cn = (j < 4) ? (tx * 4 + j) : (64 + tx * 4 + (j - 4));
            int colg = bn * 128 + cn;
            float v = acc[i][j] + bO[colg] + x[row * DMODEL + colg];
            out[row * DMODEL + colg] = v;
        }
    }
}

// ---------------------------------------------------------------------------
extern "C" void kernel_launch(void* const* d_in, const int* in_sizes, int n_in,
                              void* d_out, int out_size) {
    const float* x      = (const float*)d_in[0];
    const float* WQ     = (const float*)d_in[1];
    const float* bQ     = (const float*)d_in[2];
    const float* WK     = (const float*)d_in[3];
    const float* bK     = (const float*)d_in[4];
    const float* WV     = (const float*)d_in[5];
    const float* bV     = (const float*)d_in[6];
    const float* WO     = (const float*)d_in[7];
    const float* bO     = (const float*)d_in[8];
    const float* Wg     = (const float*)d_in[9];
    const float* bg     = (const float*)d_in[10];
    const float* alpha  = (const float*)d_in[11];
    const float* gamma  = (const float*)d_in[12];
    const float* beta   = (const float*)d_in[13];
    float* out = (float*)d_out;

    // chunk_output needs ~100KB dynamic smem (idempotent; not a stream op)
    cudaFuncSetAttribute(chunk_output, cudaFuncAttributeMaxDynamicSharedMemorySize, 100 * 1024);

    ln_kernel<<<MROWS, 256>>>(x, gamma, beta);

    dim3 g1(DQKVG / 128, MROWS / 128);
    gemm_qkvg<<<g1, 256>>>(WQ, bQ, WK, bK, WV, bV, Wg, bg);

    int nblk = BATCHSZ * NHEADS * NCHUNK;            // 2048
    chunk_summary<<<nblk, 256>>>(alpha);
    chunk_combine<<<BATCHSZ * NHEADS, 256>>>(alpha);
    chunk_output<<<nblk, 256, 99840>>>(alpha);

    dim3 g2(DMODEL / 128, MROWS / 128);
    gemm_out<<<g2, 256>>>(WO, bO, x, out);
}

// round 6
// speedup vs baseline: 3.9224x; 2.4338x over previous
#include <cuda_runtime.h>
#include <math.h>
#include <stdint.h>

// Problem dims
#define MROWS   8192      // B*T
#define DMODEL  1024
#define DQKVG   4096
#define NHEADS  16
#define DHEAD   64
#define TLEN    2048
#define BATCHSZ 4
#define CHUNK   64
#define NCHUNK  (TLEN / CHUNK)   // 32

// mma.sync tf32 GEMM tiling
#define KDIM    1024
#define BK      32
#define NKCH    (KDIM / BK)      // 32
#define ASTRIDE 36               // padded row stride (floats) -> conflict-free frags
#define ABUF    (128 * ASTRIDE)  // words per A (or B) buffer
#define STAGEU  (2 * ABUF)       // words per stage (A+B)
#define GEMM_SMEM (2 * STAGEU * 4)   // 73728 bytes

// Scratch (device globals — allocation-free per harness rules)
__device__ __align__(256) float g_xn[(size_t)MROWS * DMODEL];
__device__ __align__(256) float g_qkvg[(size_t)MROWS * DQKVG];
__device__ __align__(256) float g_og[(size_t)MROWS * DMODEL];
__device__ __align__(256) float g_chunkS[(size_t)BATCHSZ * NHEADS * NCHUNK * 64 * 64];
__device__ __align__(256) float g_state [(size_t)BATCHSZ * NHEADS * NCHUNK * 64 * 64];

// ---------------------------------------------------------------------------
// tf32 mma.sync helpers
// ---------------------------------------------------------------------------
__device__ __forceinline__ uint32_t f2tf32(float x) {
    uint32_t y;
    asm("cvt.rna.tf32.f32 %0, %1;" : "=r"(y) : "f"(x));
    return y;
}
__device__ __forceinline__ void mma_tf32(float* d, const uint32_t* a, const uint32_t* b) {
    asm volatile(
        "mma.sync.aligned.m16n8k8.row.col.f32.tf32.tf32.f32 "
        "{%0,%1,%2,%3}, {%4,%5,%6,%7}, {%8,%9}, {%0,%1,%2,%3};\n"
        : "+f"(d[0]), "+f"(d[1]), "+f"(d[2]), "+f"(d[3])
        : "r"(a[0]), "r"(a[1]), "r"(a[2]), "r"(a[3]), "r"(b[0]), "r"(b[1]));
}

// load one BKx128 A tile + BKx128 B tile worth of gmem into regs (8 float4/thread)
__device__ __forceinline__ void g_load(const float* __restrict__ Ag,
                                       const float* __restrict__ Bg,
                                       int k0, int r0, int c4,
                                       float4 stA[4], float4 stB[4]) {
    #pragma unroll
    for (int i = 0; i < 4; i++) {
        stA[i] = *(const float4*)(Ag + (size_t)(r0 + 32 * i) * KDIM + k0 + c4 * 4);
        stB[i] = *(const float4*)(Bg + (size_t)(r0 + 32 * i) * KDIM + k0 + c4 * 4);
    }
}
__device__ __forceinline__ void s_store(uint32_t* sm, int buf, int r0, int c4,
                                        const float4 stA[4], const float4 stB[4]) {
    uint32_t* As = sm + buf * STAGEU;
    uint32_t* Bs = As + ABUF;
    #pragma unroll
    for (int i = 0; i < 4; i++) {
        uint4 va = make_uint4(f2tf32(stA[i].x), f2tf32(stA[i].y),
                              f2tf32(stA[i].z), f2tf32(stA[i].w));
        *(uint4*)&As[(r0 + 32 * i) * ASTRIDE + c4 * 4] = va;
        uint4 vb = make_uint4(f2tf32(stB[i].x), f2tf32(stB[i].y),
                              f2tf32(stB[i].z), f2tf32(stB[i].w));
        *(uint4*)&Bs[(r0 + 32 * i) * ASTRIDE + c4 * 4] = vb;
    }
}
__device__ __forceinline__ void s_compute(const uint32_t* sm, int buf,
                                          int lane, int wm, int wn,
                                          float acc[4][4][4]) {
    const uint32_t* As = sm + buf * STAGEU;
    const uint32_t* Bs = As + ABUF;
    int mbase = wm * 64 + (lane >> 2);
    int nbase = wn * 32 + (lane >> 2);
    int kq = lane & 3;
    #pragma unroll
    for (int kk = 0; kk < 4; kk++) {
        int k0 = kk * 8 + kq;
        uint32_t a[4][4], b[4][2];
        #pragma unroll
        for (int mt = 0; mt < 4; mt++) {
            a[mt][0] = As[(mbase + mt * 16    ) * ASTRIDE + k0];
            a[mt][1] = As[(mbase + mt * 16 + 8) * ASTRIDE + k0];
            a[mt][2] = As[(mbase + mt * 16    ) * ASTRIDE + k0 + 4];
            a[mt][3] = As[(mbase + mt * 16 + 8) * ASTRIDE + k0 + 4];
        }
        #pragma unroll
        for (int nt = 0; nt < 4; nt++) {
            b[nt][0] = Bs[(nbase + nt * 8) * ASTRIDE + k0];
            b[nt][1] = Bs[(nbase + nt * 8) * ASTRIDE + k0 + 4];
        }
        #pragma unroll
        for (int mt = 0; mt < 4; mt++)
            #pragma unroll
            for (int nt = 0; nt < 4; nt++)
                mma_tf32(acc[mt][nt], a[mt], b[nt]);
    }
}

// full mainloop: acc = A[128xK] * B[128xK]^T
__device__ __forceinline__ void tf32_mainloop(const float* __restrict__ Ag,
                                              const float* __restrict__ Bg,
                                              uint32_t* sm, int tid,
                                              float acc[4][4][4]) {
    int lane = tid & 31, warp = tid >> 5;
    int wm = warp & 1, wn = warp >> 1;
    int r0 = tid >> 3, c4 = tid & 7;

    float4 stA[4], stB[4];
    g_load(Ag, Bg, 0, r0, c4, stA, stB);
    s_store(sm, 0, r0, c4, stA, stB);
    __syncthreads();

    for (int c = 0; c < NKCH; c++) {
        if (c + 1 < NKCH) g_load(Ag, Bg, (c + 1) * BK, r0, c4, stA, stB);
        s_compute(sm, c & 1, lane, wm, wn, acc);
        if (c + 1 < NKCH) s_store(sm, (c + 1) & 1, r0, c4, stA, stB);
        __syncthreads();
    }
}

// ---------------------------------------------------------------------------
// GEMM 1: g_qkvg = g_xn @ [WQ;WK;WV;Wg]^T + bias (+silu on G block)
// grid = (DQKVG/128 = 32, MROWS/128 = 64), 256 threads
// ---------------------------------------------------------------------------
__global__ __launch_bounds__(256)
void tc_gemm_qkvg(const float* __restrict__ WQ, const float* __restrict__ bQ,
                  const float* __restrict__ WK, const float* __restrict__ bK,
                  const float* __restrict__ WV, const float* __restrict__ bV,
                  const float* __restrict__ Wg, const float* __restrict__ bg) {
    extern __shared__ uint32_t sm[];
    int tid = threadIdx.x;
    int lane = tid & 31, warp = tid >> 5;
    int wm = warp & 1, wn = warp >> 1;
    int bn = blockIdx.x, bm = blockIdx.y;

    int cb = bn * 128;
    int which = cb >> 10;
    const float* W;  const float* bias;
    if      (which == 0) { W = WQ; bias = bQ; }
    else if (which == 1) { W = WK; bias = bK; }
    else if (which == 2) { W = WV; bias = bV; }
    else                 { W = Wg; bias = bg; }
    const float* Bg = W + (size_t)(cb & 1023) * KDIM;
    const float* Ag = g_xn + (size_t)(bm * 128) * KDIM;

    float acc[4][4][4];
    #pragma unroll
    for (int i = 0; i < 4; i++)
        #pragma unroll
        for (int j = 0; j < 4; j++)
            #pragma unroll
            for (int k = 0; k < 4; k++) acc[i][j][k] = 0.f;

    tf32_mainloop(Ag, Bg, sm, tid, acc);

    bool do_silu = (which == 3);
    int row0 = bm * 128 + wm * 64 + (lane >> 2);
    int col0 = cb + wn * 32 + (lane & 3) * 2;
    #pragma unroll
    for (int mt = 0; mt < 4; mt++) {
        #pragma unroll
        for (int nt = 0; nt < 4; nt++) {
            int cg = col0 + nt * 8;
            float b0 = bias[cg & 1023], b1 = bias[(cg + 1) & 1023];
            #pragma unroll
            for (int half = 0; half < 2; half++) {
                size_t row = (size_t)(row0 + mt * 16 + half * 8);
                float v0 = acc[mt][nt][half * 2 + 0] + b0;
                float v1 = acc[mt][nt][half * 2 + 1] + b1;
                if (do_silu) {
                    v0 = v0 / (1.0f + expf(-v0));
                    v1 = v1 / (1.0f + expf(-v1));
                }
                float2 v = make_float2(v0, v1);
                *(float2*)(g_qkvg + row * DQKVG + cg) = v;
            }
        }
    }
}

// ---------------------------------------------------------------------------
// GEMM 2: out = g_og @ WO^T + bO + x   grid = (8, 64)
// ---------------------------------------------------------------------------
__global__ __launch_bounds__(256)
void tc_gemm_out(const float* __restrict__ WO, const float* __restrict__ bO,
                 const float* __restrict__ x, float* __restrict__ out) {
    extern __shared__ uint32_t sm[];
    int tid = threadIdx.x;
    int lane = tid & 31, warp = tid >> 5;
    int wm = warp & 1, wn = warp >> 1;
    int bn = blockIdx.x, bm = blockIdx.y;

    int cb = bn * 128;
    const float* Bg = WO + (size_t)cb * KDIM;
    const float* Ag = g_og + (size_t)(bm * 128) * KDIM;

    float acc[4][4][4];
    #pragma unroll
    for (int i = 0; i < 4; i++)
        #pragma unroll
        for (int j = 0; j < 4; j++)
            #pragma unroll
            for (int k = 0; k < 4; k++) acc[i][j][k] = 0.f;

    tf32_mainloop(Ag, Bg, sm, tid, acc);

    int row0 = bm * 128 + wm * 64 + (lane >> 2);
    int col0 = cb + wn * 32 + (lane & 3) * 2;
    #pragma unroll
    for (int mt = 0; mt < 4; mt++) {
        #pragma unroll
        for (int nt = 0; nt < 4; nt++) {
            int cg = col0 + nt * 8;
            float b0 = bO[cg], b1 = bO[cg + 1];
            #pragma unroll
            for (int half = 0; half < 2; half++) {
                size_t row = (size_t)(row0 + mt * 16 + half * 8);
                float2 xr = *(const float2*)(x + row * DMODEL + cg);
                float2 v;
                v.x = acc[mt][nt][half * 2 + 0] + b0 + xr.x;
                v.y = acc[mt][nt][half * 2 + 1] + b1 + xr.y;
                *(float2*)(out + row * DMODEL + cg) = v;
            }
        }
    }
}

// ---------------------------------------------------------------------------
// LayerNorm (unchanged)
// ---------------------------------------------------------------------------
__global__ __launch_bounds__(256) void ln_kernel(const float* __restrict__ x,
                                                 const float* __restrict__ gamma,
                                                 const float* __restrict__ beta) {
    int row = blockIdx.x;
    int t = threadIdx.x;
    const float4* xr = (const float4*)(x + (size_t)row * DMODEL);
    float4 a = xr[t];
    float s = a.x + a.y + a.z + a.w;
    float q = a.x * a.x + a.y * a.y + a.z * a.z + a.w * a.w;
    #pragma unroll
    for (int o = 16; o > 0; o >>= 1) {
        s += __shfl_xor_sync(0xffffffffu, s, o);
        q += __shfl_xor_sync(0xffffffffu, q, o);
    }
    __shared__ float ss[8], sq[8];
    int w = t >> 5, lane = t & 31;
    if (lane == 0) { ss[w] = s; sq[w] = q; }
    __syncthreads();
    float st = 0.f, qt = 0.f;
    #pragma unroll
    for (int i = 0; i < 8; i++) { st += ss[i]; qt += sq[i]; }
    float mu = st * (1.0f / DMODEL);
    float var = qt * (1.0f / DMODEL) - mu * mu;
    float rs = rsqrtf(var + 1e-5f);
    float4 gm = ((const float4*)gamma)[t];
    float4 bt = ((const float4*)beta)[t];
    float4 o;
    o.x = (a.x - mu) * rs * gm.x + bt.x;
    o.y = (a.y - mu) * rs * gm.y + bt.y;
    o.z = (a.z - mu) * rs * gm.z + bt.z;
    o.w = (a.w - mu) * rs * gm.w + bt.w;
    ((float4*)(g_xn + (size_t)row * DMODEL))[t] = o;
}

// ---------------------------------------------------------------------------
// Pass 1: per-chunk state summary (unchanged)
// ---------------------------------------------------------------------------
__global__ __launch_bounds__(256) void chunk_summary(const float* __restrict__ alpha_logit) {
    int c = blockIdx.x & (NCHUNK - 1);
    int h = (blockIdx.x >> 5) & (NHEADS - 1);
    int b = blockIdx.x >> 9;

    __shared__ float Kt[64][65];
    __shared__ float Vs[64][65];
    __shared__ float lal[64];

    int tid = threadIdx.x;
    int tx = tid & 15, ty = tid >> 4;

    if (tid < 64) {
        float a = 1.0f / (1.0f + expf(-alpha_logit[h * 64 + tid]));
        lal[tid] = log2f(a);
    }
    __syncthreads();

    const float* rowb = g_qkvg + ((size_t)(b * TLEN + c * CHUNK)) * DQKVG + h * 64;
    #pragma unroll
    for (int i = 0; i < 4; i++) {
        int idx = tid + i * 256;
        int u = idx >> 4;
        int s4 = (idx & 15) << 2;
        const float* r = rowb + (size_t)u * DQKVG;
        float4 kv = *(const float4*)(r + 1024 + s4);
        float4 vv = *(const float4*)(r + 2048 + s4);
        float e = (float)(63 - u);
        Kt[u][s4 + 0] = kv.x * exp2f(lal[s4 + 0] * e);
        Kt[u][s4 + 1] = kv.y * exp2f(lal[s4 + 1] * e);
        Kt[u][s4 + 2] = kv.z * exp2f(lal[s4 + 2] * e);
        Kt[u][s4 + 3] = kv.w * exp2f(lal[s4 + 3] * e);
        Vs[u][s4 + 0] = vv.x;
        Vs[u][s4 + 1] = vv.y;
        Vs[u][s4 + 2] = vv.z;
        Vs[u][s4 + 3] = vv.w;
    }
    __syncthreads();

    float acc[4][4];
    #pragma unroll
    for (int i = 0; i < 4; i++)
        #pragma unroll
        for (int j = 0; j < 4; j++) acc[i][j] = 0.f;

    #pragma unroll 8
    for (int u = 0; u < 64; u++) {
        float ra[4], rb[4];
        #pragma unroll
        for (int i = 0; i < 4; i++) {
            ra[i] = Kt[u][ty * 4 + i];
            rb[i] = Vs[u][tx * 4 + i];
        }
        #pragma unroll
        for (int i = 0; i < 4; i++)
            #pragma unroll
            for (int j = 0; j < 4; j++)
                acc[i][j] = fmaf(ra[i], rb[j], acc[i][j]);
    }

    size_t ob = ((size_t)((b * NHEADS + h) * NCHUNK + c)) * 4096;
    #pragma unroll
    for (int i = 0; i < 4; i++)
        #pragma unroll
        for (int j = 0; j < 4; j++)
            g_chunkS[ob + (ty * 4 + i) * 64 + tx * 4 + j] = acc[i][j];
}

// ---------------------------------------------------------------------------
// Pass 2: sequential combine (unchanged)
// ---------------------------------------------------------------------------
__global__ __launch_bounds__(256) void chunk_combine(const float* __restrict__ alpha_logit) {
    int bh = blockIdx.x;
    int h = bh & (NHEADS - 1);
    int tid = threadIdx.x;

    float4 H[4];
    float aL[4];
    #pragma unroll
    for (int k = 0; k < 4; k++) {
        H[k] = make_float4(0.f, 0.f, 0.f, 0.f);
        int s = (tid + k * 256) >> 4;
        float a = 1.0f / (1.0f + expf(-alpha_logit[h * 64 + s]));
        aL[k] = exp2f(log2f(a) * 64.0f);
    }

    for (int c = 0; c < NCHUNK; c++) {
        size_t base = ((size_t)bh * NCHUNK + c) * 4096;
        #pragma unroll
        for (int k = 0; k < 4; k++) {
            int idx4 = tid + k * 256;
            ((float4*)(g_state + base))[idx4] = H[k];
            float4 S = ((const float4*)(g_chunkS + base))[idx4];
            H[k].x = aL[k] * H[k].x + S.x;
            H[k].y = aL[k] * H[k].y + S.y;
            H[k].z = aL[k] * H[k].z + S.z;
            H[k].w = aL[k] * H[k].w + S.w;
        }
    }
}

// ---------------------------------------------------------------------------
// Pass 3: intra-chunk output (unchanged)
// ---------------------------------------------------------------------------
__global__ __launch_bounds__(256) void chunk_output(const float* __restrict__ alpha_logit) {
    extern __shared__ float smf[];
    float (*Qt)[65] = (float(*)[65])(smf);
    float (*Ks)[65] = (float(*)[65])(smf + 4160);
    float (*Ms)[65] = (float(*)[65])(smf + 8320);
    float (*NN)[65] = (float(*)[65])(smf + 16640);

    __shared__ float al[64], lal[64];

    int c = blockIdx.x & (NCHUNK - 1);
    int h = (blockIdx.x >> 5) & (NHEADS - 1);
    int b = blockIdx.x >> 9;

    int tid = threadIdx.x;
    int tx = tid & 15, ty = tid >> 4;

    if (tid < 64) {
        float a = 1.0f / (1.0f + expf(-alpha_logit[h * 64 + tid]));
        al[tid] = a;
        lal[tid] = log2f(a);
    }
    __syncthreads();

    const float* rowb = g_qkvg + ((size_t)(b * TLEN + c * CHUNK)) * DQKVG + h * 64;
    size_t sbase = ((size_t)((b * NHEADS + h) * NCHUNK + c)) * 4096;

    #pragma unroll
    for (int i = 0; i < 4; i++) {
        int idx = tid + i * 256;
        int t = idx >> 4;
        int s4 = (idx & 15) << 2;
        const float* r = rowb + (size_t)t * DQKVG;
        float4 qv = *(const float4*)(r + s4);
        float4 kv = *(const float4*)(r + 1024 + s4);
        float4 vv = *(const float4*)(r + 2048 + s4);
        float tf = (float)t;
        Qt[s4 + 0][t] = qv.x * exp2f(lal[s4 + 0] * tf);
        Qt[s4 + 1][t] = qv.y * exp2f(lal[s4 + 1] * tf);
        Qt[s4 + 2][t] = qv.z * exp2f(lal[s4 + 2] * tf);
        Qt[s4 + 3][t] = qv.w * exp2f(lal[s4 + 3] * tf);
        Ks[s4 + 0][t] = kv.x * exp2f(-lal[s4 + 0] * tf);
        Ks[s4 + 1][t] = kv.y * exp2f(-lal[s4 + 1] * tf);
        Ks[s4 + 2][t] = kv.z * exp2f(-lal[s4 + 2] * tf);
        Ks[s4 + 3][t] = kv.w * exp2f(-lal[s4 + 3] * tf);
        NN[t][s4 + 0] = vv.x;
        NN[t][s4 + 1] = vv.y;
        NN[t][s4 + 2] = vv.z;
        NN[t][s4 + 3] = vv.w;
        float4 hv = *(const float4*)(g_state + sbase + (size_t)idx * 4);
        NN[64 + t][s4 + 0] = hv.x;
        NN[64 + t][s4 + 1] = hv.y;
        NN[64 + t][s4 + 2] = hv.z;
        NN[64 + t][s4 + 3] = hv.w;
    }
    __syncthreads();

    float acc[4][4];
    #pragma unroll
    for (int i = 0; i < 4; i++)
        #pragma unroll
        for (int j = 0; j < 4; j++) acc[i][j] = 0.f;

    #pragma unroll 8
    for (int s = 0; s < 64; s++) {
        float ra[4], rb[4];
        #pragma unroll
        for (int i = 0; i < 4; i++) {
            ra[i] = Qt[s][ty * 4 + i];
            rb[i] = Ks[s][tx * 4 + i];
        }
        #pragma unroll
        for (int i = 0; i < 4; i++)
            #pragma unroll
            for (int j = 0; j < 4; j++)
                acc[i][j] = fmaf(ra[i], rb[j], acc[i][j]);
    }

    #pragma unroll
    for (int i = 0; i < 4; i++) {
        int t = ty * 4 + i;
        #pragma unroll
        for (int j = 0; j < 4; j++) {
            int u = tx * 4 + j;
            Ms[u][t] = (u <= t) ? acc[i][j] : 0.f;
        }
    }
    #pragma unroll
    for (int i = 0; i < 4; i++) {
        int idx = tid + i * 256;
        int s = idx >> 4;
        int t4 = (idx & 15) << 2;
        float a = al[s];
        #pragma unroll
        for (int j = 0; j < 4; j++)
            Ms[64 + s][t4 + j] = Qt[s][t4 + j] * a;
    }
    __syncthreads();

    float o[4][4];
    #pragma unroll
    for (int i = 0; i < 4; i++)
        #pragma unroll
        for (int j = 0; j < 4; j++) o[i][j] = 0.f;

    #pragma unroll 8
    for (int jj = 0; jj < 128; jj++) {
        float ra[4], rb[4];
        #pragma unroll
        for (int i = 0; i < 4; i++) {
            ra[i] = Ms[jj][ty * 4 + i];
            rb[i] = NN[jj][tx * 4 + i];
        }
        #pragma unroll
        for (int i = 0; i < 4; i++)
            #pragma unroll
            for (int j = 0; j < 4; j++)
                o[i][j] = fmaf(ra[i], rb[j], o[i][j]);
    }

    float* ogb = g_og + ((size_t)(b * TLEN + c * CHUNK)) * DMODEL + h * 64;
    #pragma unroll
    for (int i = 0; i < 4; i++) {
        int t = ty * 4 + i;
        const float* gr = rowb + (size_t)t * DQKVG + 3072 + tx * 4;
        float4 g = *(const float4*)gr;
        float4 ov;
        ov.x = o[i][0] * g.x;
        ov.y = o[i][1] * g.y;
        ov.z = o[i][2] * g.z;
        ov.w = o[i][3] * g.w;
        *(float4*)(ogb + (size_t)t * DMODEL + tx * 4) = ov;
    }
}

// ---------------------------------------------------------------------------
extern "C" void kernel_launch(void* const* d_in, const int* in_sizes, int n_in,
                              void* d_out, int out_size) {
    const float* x      = (const float*)d_in[0];
    const float* WQ     = (const float*)d_in[1];
    const float* bQ     = (const float*)d_in[2];
    const float* WK     = (const float*)d_in[3];
    const float* bK     = (const float*)d_in[4];
    const float* WV     = (const float*)d_in[5];
    const float* bV     = (const float*)d_in[6];
    const float* WO     = (const float*)d_in[7];
    const float* bO     = (const float*)d_in[8];
    const float* Wg     = (const float*)d_in[9];
    const float* bg     = (const float*)d_in[10];
    const float* alpha  = (const float*)d_in[11];
    const float* gamma  = (const float*)d_in[12];
    const float* beta   = (const float*)d_in[13];
    float* out = (float*)d_out;

    cudaFuncSetAttribute(chunk_output, cudaFuncAttributeMaxDynamicSharedMemorySize, 100 * 1024);
    cudaFuncSetAttribute(tc_gemm_qkvg, cudaFuncAttributeMaxDynamicSharedMemorySize, GEMM_SMEM);
    cudaFuncSetAttribute(tc_gemm_out,  cudaFuncAttributeMaxDynamicSharedMemorySize, GEMM_SMEM);

    ln_kernel<<<MROWS, 256>>>(x, gamma, beta);

    dim3 g1(DQKVG / 128, MROWS / 128);   // (32, 64)
    tc_gemm_qkvg<<<g1, 256, GEMM_SMEM>>>(WQ, bQ, WK, bK, WV, bV, Wg, bg);

    int nblk = BATCHSZ * NHEADS * NCHUNK;            // 2048
    chunk_summary<<<nblk, 256>>>(alpha);
    chunk_combine<<<BATCHSZ * NHEADS, 256>>>(alpha);
    chunk_output<<<nblk, 256, 99840>>>(alpha);

    dim3 g2(DMODEL / 128, MROWS / 128);  // (8, 64)
    tc_gemm_out<<<g2, 256, GEMM_SMEM>>>(WO, bO, x, out);
}

// round 8
// speedup vs baseline: 4.2395x; 1.0808x over previous
#include <cuda_runtime.h>
#include <math.h>
#include <stdint.h>

// Problem dims
#define MROWS   8192      // B*T
#define DMODEL  1024
#define DQKVG   4096
#define NHEADS  16
#define DHEAD   64
#define TLEN    2048
#define BATCHSZ 4
#define CHUNK   64
#define NCHUNK  (TLEN / CHUNK)   // 32

// mma.sync tf32 GEMM tiling
#define KDIM    1024
#define BK      32
#define NKCH    (KDIM / BK)      // 32
#define ASTRIDE 36               // padded row stride (floats) -> conflict-free frags
#define ABUF    (128 * ASTRIDE)  // words per A (or B) buffer within a stage
#define STAGEU  (2 * ABUF)       // words per stage (A+B) = 9216
#define NSTAGE  3
#define GEMM_SMEM (NSTAGE * STAGEU * 4)   // 110592 bytes

// Scratch (device globals — allocation-free per harness rules)
__device__ __align__(256) float g_xn[(size_t)MROWS * DMODEL];
__device__ __align__(256) float g_qkvg[(size_t)MROWS * DQKVG];
__device__ __align__(256) float g_og[(size_t)MROWS * DMODEL];
__device__ __align__(256) float g_chunkS[(size_t)BATCHSZ * NHEADS * NCHUNK * 64 * 64];
__device__ __align__(256) float g_state [(size_t)BATCHSZ * NHEADS * NCHUNK * 64 * 64];
// tf32-pre-rounded weights: [WQ;WK;WV;Wg] and WO
__device__ __align__(256) float g_wt [(size_t)DQKVG * KDIM];
__device__ __align__(256) float g_wot[(size_t)DMODEL * KDIM];

// ---------------------------------------------------------------------------
// helpers
// ---------------------------------------------------------------------------
__device__ __forceinline__ uint32_t f2tf32(float x) {
    uint32_t y;
    asm("cvt.rna.tf32.f32 %0, %1;" : "=r"(y) : "f"(x));
    return y;
}
__device__ __forceinline__ float f2tf32f(float x) {
    return __uint_as_float(f2tf32(x));
}
__device__ __forceinline__ uint32_t smem_u32(const void* p) {
    uint32_t a;
    asm("{ .reg .u64 t; cvta.to.shared.u64 t, %1; cvt.u32.u64 %0, t; }" : "=r"(a) : "l"(p));
    return a;
}
__device__ __forceinline__ void mma_tf32(float* d, const uint32_t* a, const uint32_t* b) {
    asm volatile(
        "mma.sync.aligned.m16n8k8.row.col.f32.tf32.tf32.f32 "
        "{%0,%1,%2,%3}, {%4,%5,%6,%7}, {%8,%9}, {%0,%1,%2,%3};\n"
        : "+f"(d[0]), "+f"(d[1]), "+f"(d[2]), "+f"(d[3])
        : "r"(a[0]), "r"(a[1]), "r"(a[2]), "r"(a[3]), "r"(b[0]), "r"(b[1]));
}
#define CP_ASYNC16(dst, src) \
    asm volatile("cp.async.cg.shared.global [%0], [%1], 16;\n" :: "r"(dst), "l"(src))
#define CP_COMMIT() asm volatile("cp.async.commit_group;\n" ::: "memory")
#define CP_WAIT2()  asm volatile("cp.async.wait_group 2;\n" ::: "memory")

// ---------------------------------------------------------------------------
// one-shot weight tf32 pre-rounding: g_wt = [WQ;WK;WV;Wg], g_wot = WO
// 5M floats total -> 1310720 float4, grid 5120 x 256
// ---------------------------------------------------------------------------
__global__ __launch_bounds__(256) void conv_weights(
    const float* __restrict__ WQ, const float* __restrict__ WK,
    const float* __restrict__ WV, const float* __restrict__ Wg,
    const float* __restrict__ WO) {
    int i = blockIdx.x * 256 + threadIdx.x;        // float4 index
    const float* src;
    float* dst;
    if (i < 1048576) {                             // 4 x 262144 float4 (qkvg)
        int m = i >> 18;
        int li = i & 262143;
        src = (m == 0 ? WQ : m == 1 ? WK : m == 2 ? WV : Wg) + (size_t)li * 4;
        dst = g_wt + (size_t)i * 4;
    } else {
        int li = i - 1048576;                      // 262144 float4 (WO)
        src = WO + (size_t)li * 4;
        dst = g_wot + (size_t)li * 4;
    }
    float4 v = *(const float4*)src;
    v.x = f2tf32f(v.x); v.y = f2tf32f(v.y);
    v.z = f2tf32f(v.z); v.w = f2tf32f(v.w);
    *(float4*)dst = v;
}

// ---------------------------------------------------------------------------
// cp.async stage issue: A[128xBK] + B[128xBK], already tf32-valid fp32 bits
// ---------------------------------------------------------------------------
__device__ __forceinline__ void issue_stage(const float* __restrict__ Ag,
                                            const float* __restrict__ Bg,
                                            uint32_t sbase, int stage, int k0,
                                            int tid) {
    uint32_t As = sbase + stage * (STAGEU * 4);
    uint32_t Bs = As + ABUF * 4;
    int r0 = tid >> 3, c4 = (tid & 7) * 4;
    #pragma unroll
    for (int i = 0; i < 4; i++) {
        int r = r0 + 32 * i;
        CP_ASYNC16(As + (r * ASTRIDE + c4) * 4, Ag + (size_t)r * KDIM + k0 + c4);
        CP_ASYNC16(Bs + (r * ASTRIDE + c4) * 4, Bg + (size_t)r * KDIM + k0 + c4);
    }
}

__device__ __forceinline__ void s_compute(const uint32_t* __restrict__ sm, int buf,
                                          int lane, int wm, int wn,
                                          float acc[4][4][4]) {
    const uint32_t* As = sm + buf * STAGEU;
    const uint32_t* Bs = As + ABUF;
    int mbase = wm * 64 + (lane >> 2);
    int nbase = wn * 32 + (lane >> 2);
    int kq = lane & 3;
    #pragma unroll
    for (int kk = 0; kk < 4; kk++) {
        int k0 = kk * 8 + kq;
        uint32_t a[4][4], b[4][2];
        #pragma unroll
        for (int mt = 0; mt < 4; mt++) {
            a[mt][0] = As[(mbase + mt * 16    ) * ASTRIDE + k0];
            a[mt][1] = As[(mbase + mt * 16 + 8) * ASTRIDE + k0];
            a[mt][2] = As[(mbase + mt * 16    ) * ASTRIDE + k0 + 4];
            a[mt][3] = As[(mbase + mt * 16 + 8) * ASTRIDE + k0 + 4];
        }
        #pragma unroll
        for (int nt = 0; nt < 4; nt++) {
            b[nt][0] = Bs[(nbase + nt * 8) * ASTRIDE + k0];
            b[nt][1] = Bs[(nbase + nt * 8) * ASTRIDE + k0 + 4];
        }
        #pragma unroll
        for (int mt = 0; mt < 4; mt++)
            #pragma unroll
            for (int nt = 0; nt < 4; nt++)
                mma_tf32(acc[mt][nt], a[mt], b[nt]);
    }
}

// full mainloop: acc = A[128xK] * B[128xK]^T, 3-stage cp.async pipeline
__device__ __forceinline__ void tf32_mainloop(const float* __restrict__ Ag,
                                              const float* __restrict__ Bg,
                                              uint32_t* sm, int tid,
                                              float acc[4][4][4]) {
    int lane = tid & 31, warp = tid >> 5;
    int wm = warp & 1, wn = warp >> 1;
    uint32_t sb = smem_u32(sm);

    issue_stage(Ag, Bg, sb, 0, 0, tid);      CP_COMMIT();
    issue_stage(Ag, Bg, sb, 1, BK, tid);     CP_COMMIT();

    #pragma unroll 1
    for (int c = 0; c < NKCH; c++) {
        if (c + 2 < NKCH) {
            int st = c + 2;
            issue_stage(Ag, Bg, sb, st % NSTAGE, st * BK, tid);
        }
        CP_COMMIT();
        CP_WAIT2();
        __syncthreads();
        s_compute(sm, c % NSTAGE, lane, wm, wn, acc);
        __syncthreads();
    }
}

// ---------------------------------------------------------------------------
// GEMM 1: g_qkvg = g_xn @ g_wt^T + bias (+silu on G block)
// grid = (32, 64), 256 threads, 2 CTAs/SM
// ---------------------------------------------------------------------------
__global__ __launch_bounds__(256, 2)
void tc_gemm_qkvg(const float* __restrict__ bQ, const float* __restrict__ bK,
                  const float* __restrict__ bV, const float* __restrict__ bg) {
    extern __shared__ uint32_t sm[];
    int tid = threadIdx.x;
    int lane = tid & 31, warp = tid >> 5;
    int wm = warp & 1, wn = warp >> 1;
    int bn = blockIdx.x, bm = blockIdx.y;

    int cb = bn * 128;
    int which = cb >> 10;
    const float* bias;
    if      (which == 0) bias = bQ;
    else if (which == 1) bias = bK;
    else if (which == 2) bias = bV;
    else                 bias = bg;
    const float* Bg = g_wt + (size_t)cb * KDIM;
    const float* Ag = g_xn + (size_t)(bm * 128) * KDIM;

    float acc[4][4][4];
    #pragma unroll
    for (int i = 0; i < 4; i++)
        #pragma unroll
        for (int j = 0; j < 4; j++)
            #pragma unroll
            for (int k = 0; k < 4; k++) acc[i][j][k] = 0.f;

    tf32_mainloop(Ag, Bg, sm, tid, acc);

    bool do_silu = (which == 3);
    int row0 = bm * 128 + wm * 64 + (lane >> 2);
    int col0 = cb + wn * 32 + (lane & 3) * 2;
    #pragma unroll
    for (int mt = 0; mt < 4; mt++) {
        #pragma unroll
        for (int nt = 0; nt < 4; nt++) {
            int cg = col0 + nt * 8;
            float b0 = bias[cg & 1023], b1 = bias[(cg + 1) & 1023];
            #pragma unroll
            for (int half = 0; half < 2; half++) {
                size_t row = (size_t)(row0 + mt * 16 + half * 8);
                float v0 = acc[mt][nt][half * 2 + 0] + b0;
                float v1 = acc[mt][nt][half * 2 + 1] + b1;
                if (do_silu) {
                    v0 = v0 / (1.0f + expf(-v0));
                    v1 = v1 / (1.0f + expf(-v1));
                }
                *(float2*)(g_qkvg + row * DQKVG + cg) = make_float2(v0, v1);
            }
        }
    }
}

// ---------------------------------------------------------------------------
// GEMM 2: out = g_og @ g_wot^T + bO + x   grid = (8, 64)
// ---------------------------------------------------------------------------
__global__ __launch_bounds__(256, 2)
void tc_gemm_out(const float* __restrict__ bO,
                 const float* __restrict__ x, float* __restrict__ out) {
    extern __shared__ uint32_t sm[];
    int tid = threadIdx.x;
    int lane = tid & 31, warp = tid >> 5;
    int wm = warp & 1, wn = warp >> 1;
    int bn = blockIdx.x, bm = blockIdx.y;

    int cb = bn * 128;
    const float* Bg = g_wot + (size_t)cb * KDIM;
    const float* Ag = g_og + (size_t)(bm * 128) * KDIM;

    float acc[4][4][4];
    #pragma unroll
    for (int i = 0; i < 4; i++)
        #pragma unroll
        for (int j = 0; j < 4; j++)
            #pragma unroll
            for (int k = 0; k < 4; k++) acc[i][j][k] = 0.f;

    tf32_mainloop(Ag, Bg, sm, tid, acc);

    int row0 = bm * 128 + wm * 64 + (lane >> 2);
    int col0 = cb + wn * 32 + (lane & 3) * 2;
    #pragma unroll
    for (int mt = 0; mt < 4; mt++) {
        #pragma unroll
        for (int nt = 0; nt < 4; nt++) {
            int cg = col0 + nt * 8;
            float b0 = bO[cg], b1 = bO[cg + 1];
            #pragma unroll
            for (int half = 0; half < 2; half++) {
                size_t row = (size_t)(row0 + mt * 16 + half * 8);
                float2 xr = *(const float2*)(x + row * DMODEL + cg);
                float2 v;
                v.x = acc[mt][nt][half * 2 + 0] + b0 + xr.x;
                v.y = acc[mt][nt][half * 2 + 1] + b1 + xr.y;
                *(float2*)(out + row * DMODEL + cg) = v;
            }
        }
    }
}

// ---------------------------------------------------------------------------
// LayerNorm: writes tf32-pre-rounded output (GEMM A operand)
// ---------------------------------------------------------------------------
__global__ __launch_bounds__(256) void ln_kernel(const float* __restrict__ x,
                                                 const float* __restrict__ gamma,
                                                 const float* __restrict__ beta) {
    int row = blockIdx.x;
    int t = threadIdx.x;
    const float4* xr = (const float4*)(x + (size_t)row * DMODEL);
    float4 a = xr[t];
    float s = a.x + a.y + a.z + a.w;
    float q = a.x * a.x + a.y * a.y + a.z * a.z + a.w * a.w;
    #pragma unroll
    for (int o = 16; o > 0; o >>= 1) {
        s += __shfl_xor_sync(0xffffffffu, s, o);
        q += __shfl_xor_sync(0xffffffffu, q, o);
    }
    __shared__ float ss[8], sq[8];
    int w = t >> 5, lane = t & 31;
    if (lane == 0) { ss[w] = s; sq[w] = q; }
    __syncthreads();
    float st = 0.f, qt = 0.f;
    #pragma unroll
    for (int i = 0; i < 8; i++) { st += ss[i]; qt += sq[i]; }
    float mu = st * (1.0f / DMODEL);
    float var = qt * (1.0f / DMODEL) - mu * mu;
    float rs = rsqrtf(var + 1e-5f);
    float4 gm = ((const float4*)gamma)[t];
    float4 bt = ((const float4*)beta)[t];
    float4 o;
    o.x = f2tf32f((a.x - mu) * rs * gm.x + bt.x);
    o.y = f2tf32f((a.y - mu) * rs * gm.y + bt.y);
    o.z = f2tf32f((a.z - mu) * rs * gm.z + bt.z);
    o.w = f2tf32f((a.w - mu) * rs * gm.w + bt.w);
    ((float4*)(g_xn + (size_t)row * DMODEL))[t] = o;
}

// ---------------------------------------------------------------------------
// Pass 1: per-chunk state summary (unchanged)
// ---------------------------------------------------------------------------
__global__ __launch_bounds__(256) void chunk_summary(const float* __restrict__ alpha_logit) {
    int c = blockIdx.x & (NCHUNK - 1);
    int h = (blockIdx.x >> 5) & (NHEADS - 1);
    int b = blockIdx.x >> 9;

    __shared__ float Kt[64][65];
    __shared__ float Vs[64][65];
    __shared__ float lal[64];

    int tid = threadIdx.x;
    int tx = tid & 15, ty = tid >> 4;

    if (tid < 64) {
        float a = 1.0f / (1.0f + expf(-alpha_logit[h * 64 + tid]));
        lal[tid] = log2f(a);
    }
    __syncthreads();

    const float* rowb = g_qkvg + ((size_t)(b * TLEN + c * CHUNK)) * DQKVG + h * 64;
    #pragma unroll
    for (int i = 0; i < 4; i++) {
        int idx = tid + i * 256;
        int u = idx >> 4;
        int s4 = (idx & 15) << 2;
        const float* r = rowb + (size_t)u * DQKVG;
        float4 kv = *(const float4*)(r + 1024 + s4);
        float4 vv = *(const float4*)(r + 2048 + s4);
        float e = (float)(63 - u);
        Kt[u][s4 + 0] = kv.x * exp2f(lal[s4 + 0] * e);
        Kt[u][s4 + 1] = kv.y * exp2f(lal[s4 + 1] * e);
        Kt[u][s4 + 2] = kv.z * exp2f(lal[s4 + 2] * e);
        Kt[u][s4 + 3] = kv.w * exp2f(lal[s4 + 3] * e);
        Vs[u][s4 + 0] = vv.x;
        Vs[u][s4 + 1] = vv.y;
        Vs[u][s4 + 2] = vv.z;
        Vs[u][s4 + 3] = vv.w;
    }
    __syncthreads();

    float acc[4][4];
    #pragma unroll
    for (int i = 0; i < 4; i++)
        #pragma unroll
        for (int j = 0; j < 4; j++) acc[i][j] = 0.f;

    #pragma unroll 8
    for (int u = 0; u < 64; u++) {
        float ra[4], rb[4];
        #pragma unroll
        for (int i = 0; i < 4; i++) {
            ra[i] = Kt[u][ty * 4 + i];
            rb[i] = Vs[u][tx * 4 + i];
        }
        #pragma unroll
        for (int i = 0; i < 4; i++)
            #pragma unroll
            for (int j = 0; j < 4; j++)
                acc[i][j] = fmaf(ra[i], rb[j], acc[i][j]);
    }

    size_t ob = ((size_t)((b * NHEADS + h) * NCHUNK + c)) * 4096;
    #pragma unroll
    for (int i = 0; i < 4; i++)
        #pragma unroll
        for (int j = 0; j < 4; j++)
            g_chunkS[ob + (ty * 4 + i) * 64 + tx * 4 + j] = acc[i][j];
}

// ---------------------------------------------------------------------------
// Pass 2: sequential combine (unchanged)
// ---------------------------------------------------------------------------
__global__ __launch_bounds__(256) void chunk_combine(const float* __restrict__ alpha_logit) {
    int bh = blockIdx.x;
    int h = bh & (NHEADS - 1);
    int tid = threadIdx.x;

    float4 H[4];
    float aL[4];
    #pragma unroll
    for (int k = 0; k < 4; k++) {
        H[k] = make_float4(0.f, 0.f, 0.f, 0.f);
        int s = (tid + k * 256) >> 4;
        float a = 1.0f / (1.0f + expf(-alpha_logit[h * 64 + s]));
        aL[k] = exp2f(log2f(a) * 64.0f);
    }

    for (int c = 0; c < NCHUNK; c++) {
        size_t base = ((size_t)bh * NCHUNK + c) * 4096;
        #pragma unroll
        for (int k = 0; k < 4; k++) {
            int idx4 = tid + k * 256;
            ((float4*)(g_state + base))[idx4] = H[k];
            float4 S = ((const float4*)(g_chunkS + base))[idx4];
            H[k].x = aL[k] * H[k].x + S.x;
            H[k].y = aL[k] * H[k].y + S.y;
            H[k].z = aL[k] * H[k].z + S.z;
            H[k].w = aL[k] * H[k].w + S.w;
        }
    }
}

// ---------------------------------------------------------------------------
// Pass 3: intra-chunk output; epilogue writes tf32-pre-rounded g_og
// ---------------------------------------------------------------------------
__global__ __launch_bounds__(256) void chunk_output(const float* __restrict__ alpha_logit) {
    extern __shared__ float smf[];
    float (*Qt)[65] = (float(*)[65])(smf);
    float (*Ks)[65] = (float(*)[65])(smf + 4160);
    float (*Ms)[65] = (float(*)[65])(smf + 8320);
    float (*NN)[65] = (float(*)[65])(smf + 16640);

    __shared__ float al[64], lal[64];

    int c = blockIdx.x & (NCHUNK - 1);
    int h = (blockIdx.x >> 5) & (NHEADS - 1);
    int b = blockIdx.x >> 9;

    int tid = threadIdx.x;
    int tx = tid & 15, ty = tid >> 4;

    if (tid < 64) {
        float a = 1.0f / (1.0f + expf(-alpha_logit[h * 64 + tid]));
        al[tid] = a;
        lal[tid] = log2f(a);
    }
    __syncthreads();

    const float* rowb = g_qkvg + ((size_t)(b * TLEN + c * CHUNK)) * DQKVG + h * 64;
    size_t sbase = ((size_t)((b * NHEADS + h) * NCHUNK + c)) * 4096;

    #pragma unroll
    for (int i = 0; i < 4; i++) {
        int idx = tid + i * 256;
        int t = idx >> 4;
        int s4 = (idx & 15) << 2;
        const float* r = rowb + (size_t)t * DQKVG;
        float4 qv = *(const float4*)(r + s4);
        float4 kv = *(const float4*)(r + 1024 + s4);
        float4 vv = *(const float4*)(r + 2048 + s4);
        float tf = (float)t;
        Qt[s4 + 0][t] = qv.x * exp2f(lal[s4 + 0] * tf);
        Qt[s4 + 1][t] = qv.y * exp2f(lal[s4 + 1] * tf);
        Qt[s4 + 2][t] = qv.z * exp2f(lal[s4 + 2] * tf);
        Qt[s4 + 3][t] = qv.w * exp2f(lal[s4 + 3] * tf);
        Ks[s4 + 0][t] = kv.x * exp2f(-lal[s4 + 0] * tf);
        Ks[s4 + 1][t] = kv.y * exp2f(-lal[s4 + 1] * tf);
        Ks[s4 + 2][t] = kv.z * exp2f(-lal[s4 + 2] * tf);
        Ks[s4 + 3][t] = kv.w * exp2f(-lal[s4 + 3] * tf);
        NN[t][s4 + 0] = vv.x;
        NN[t][s4 + 1] = vv.y;
        NN[t][s4 + 2] = vv.z;
        NN[t][s4 + 3] = vv.w;
        float4 hv = *(const float4*)(g_state + sbase + (size_t)idx * 4);
        NN[64 + t][s4 + 0] = hv.x;
        NN[64 + t][s4 + 1] = hv.y;
        NN[64 + t][s4 + 2] = hv.z;
        NN[64 + t][s4 + 3] = hv.w;
    }
    __syncthreads();

    float acc[4][4];
    #pragma unroll
    for (int i = 0; i < 4; i++)
        #pragma unroll
        for (int j = 0; j < 4; j++) acc[i][j] = 0.f;

    #pragma unroll 8
    for (int s = 0; s < 64; s++) {
        float ra[4], rb[4];
        #pragma unroll
        for (int i = 0; i < 4; i++) {
            ra[i] = Qt[s][ty * 4 + i];
            rb[i] = Ks[s][tx * 4 + i];
        }
        #pragma unroll
        for (int i = 0; i < 4; i++)
            #pragma unroll
            for (int j = 0; j < 4; j++)
                acc[i][j] = fmaf(ra[i], rb[j], acc[i][j]);
    }

    #pragma unroll
    for (int i = 0; i < 4; i++) {
        int t = ty * 4 + i;
        #pragma unroll
        for (int j = 0; j < 4; j++) {
            int u = tx * 4 + j;
            Ms[u][t] = (u <= t) ? acc[i][j] : 0.f;
        }
    }
    #pragma unroll
    for (int i = 0; i < 4; i++) {
        int idx = tid + i * 256;
        int s = idx >> 4;
        int t4 = (idx & 15) << 2;
        float a = al[s];
        #pragma unroll
        for (int j = 0; j < 4; j++)
            Ms[64 + s][t4 + j] = Qt[s][t4 + j] * a;
    }
    __syncthreads();

    float o[4][4];
    #pragma unroll
    for (int i = 0; i < 4; i++)
        #pragma unroll
        for (int j = 0; j < 4; j++) o[i][j] = 0.f;

    #pragma unroll 8
    for (int jj = 0; jj < 128; jj++) {
        float ra[4], rb[4];
        #pragma unroll
        for (int i = 0; i < 4; i++) {
            ra[i] = Ms[jj][ty * 4 + i];
            rb[i] = NN[jj][tx * 4 + i];
        }
        #pragma unroll
        for (int i = 0; i < 4; i++)
            #pragma unroll
            for (int j = 0; j < 4; j++)
                o[i][j] = fmaf(ra[i], rb[j], o[i][j]);
    }

    float* ogb = g_og + ((size_t)(b * TLEN + c * CHUNK)) * DMODEL + h * 64;
    #pragma unroll
    for (int i = 0; i < 4; i++) {
        int t = ty * 4 + i;
        const float* gr = rowb + (size_t)t * DQKVG + 3072 + tx * 4;
        float4 g = *(const float4*)gr;
        float4 ov;
        ov.x = f2tf32f(o[i][0] * g.x);
        ov.y = f2tf32f(o[i][1] * g.y);
        ov.z = f2tf32f(o[i][2] * g.z);
        ov.w = f2tf32f(o[i][3] * g.w);
        *(float4*)(ogb + (size_t)t * DMODEL + tx * 4) = ov;
    }
}

// ---------------------------------------------------------------------------
extern "C" void kernel_launch(void* const* d_in, const int* in_sizes, int n_in,
                              void* d_out, int out_size) {
    const float* x      = (const float*)d_in[0];
    const float* WQ     = (const float*)d_in[1];
    const float* bQ     = (const float*)d_in[2];
    const float* WK     = (const float*)d_in[3];
    const float* bK     = (const float*)d_in[4];
    const float* WV     = (const float*)d_in[5];
    const float* bV     = (const float*)d_in[6];
    const float* WO     = (const float*)d_in[7];
    const float* bO     = (const float*)d_in[8];
    const float* Wg     = (const float*)d_in[9];
    const float* bg     = (const float*)d_in[10];
    const float* alpha  = (const float*)d_in[11];
    const float* gamma  = (const float*)d_in[12];
    const float* beta   = (const float*)d_in[13];
    float* out = (float*)d_out;

    cudaFuncSetAttribute(chunk_output, cudaFuncAttributeMaxDynamicSharedMemorySize, 100 * 1024);
    cudaFuncSetAttribute(tc_gemm_qkvg, cudaFuncAttributeMaxDynamicSharedMemorySize, GEMM_SMEM);
    cudaFuncSetAttribute(tc_gemm_out,  cudaFuncAttributeMaxDynamicSharedMemorySize, GEMM_SMEM);

    conv_weights<<<5120, 256>>>(WQ, WK, WV, Wg, WO);
    ln_kernel<<<MROWS, 256>>>(x, gamma, beta);

    dim3 g1(DQKVG / 128, MROWS / 128);   // (32, 64)
    tc_gemm_qkvg<<<g1, 256, GEMM_SMEM>>>(bQ, bK, bV, bg);

    int nblk = BATCHSZ * NHEADS * NCHUNK;            // 2048
    chunk_summary<<<nblk, 256>>>(alpha);
    chunk_combine<<<BATCHSZ * NHEADS, 256>>>(alpha);
    chunk_output<<<nblk, 256, 99840>>>(alpha);

    dim3 g2(DMODEL / 128, MROWS / 128);  // (8, 64)
    tc_gemm_out<<<g2, 256, GEMM_SMEM>>>(bO, x, out);
}